// round 1
// baseline (speedup 1.0000x reference)
#include <cuda_runtime.h>

// Scratch (allocation-free rule: __device__ globals)
__device__ float g_t[8 * 256 * 128];     // t = adj_avg @ x
__device__ float g_n1[2048 * 8];         // n1[row][k], padded stride 8
__device__ float g_n2[2048 * 8];
__device__ float g_WwT[128 * 128];       // W_w transposed  [k][d]
__device__ float g_WxxT[128 * 128];      // Wxx_w transposed [k][d]

// ---------------------------------------------------------------------------
// Transpose W_w and Wxx_w (tiny; classic 32x32 smem tile)
// grid 32 blocks, block (32,8). blocks 0..15 -> W_w, 16..31 -> Wxx_w
// ---------------------------------------------------------------------------
__global__ void k_transpose(const float* __restrict__ Ww,
                            const float* __restrict__ Wxx) {
    __shared__ float tile[32][33];
    int m  = blockIdx.x >> 4;
    int t  = blockIdx.x & 15;
    int tr = (t >> 2) * 32, tc = (t & 3) * 32;
    const float* src = m ? Wxx : Ww;
    float*       dst = m ? g_WxxT : g_WwT;
    int tx = threadIdx.x, ty = threadIdx.y;
    #pragma unroll
    for (int r = ty; r < 32; r += 8)
        tile[r][tx] = src[(tr + r) * 128 + tc + tx];
    __syncthreads();
    #pragma unroll
    for (int r = ty; r < 32; r += 8)
        dst[(tc + r) * 128 + tr + tx] = tile[tx][r];   // dst[k*128+d] = src[d*128+k]
}

// ---------------------------------------------------------------------------
// t[b,i,d] = sum_j mean_h(wa[b,h,i,j]) * x[b,j,d]
// grid = B * (L/8) = 256 blocks, 128 threads (thread = d), 8 rows per block
// ---------------------------------------------------------------------------
__global__ void __launch_bounds__(128) k_gcn_agg(const float* __restrict__ x,
                                                 const float* __restrict__ wa) {
    __shared__ float x_s[32 * 128];   // x tile [jj][d]
    __shared__ float a_s[8 * 32];     // adj_avg tile [ii][jj]
    int b   = blockIdx.x >> 5;
    int i0  = (blockIdx.x & 31) << 3;
    int tid = threadIdx.x;
    const float inv6 = 1.0f / 6.0f;

    float acc[8];
    #pragma unroll
    for (int ii = 0; ii < 8; ii++) acc[ii] = 0.0f;

    for (int j0 = 0; j0 < 256; j0 += 32) {
        // coalesced x tile copy (32 rows x 128 floats = contiguous)
        const float4* xs = (const float4*)(x + ((long)b * 256 + j0) * 128);
        float4*       xd = (float4*)x_s;
        #pragma unroll
        for (int idx = tid; idx < 1024; idx += 128) xd[idx] = xs[idx];
        // adj_avg tile: 256 entries, each = mean over 6 h (coalesced across jj)
        #pragma unroll
        for (int ent = tid; ent < 256; ent += 128) {
            int ii = ent >> 5, jj = ent & 31;
            float s = 0.0f;
            #pragma unroll
            for (int h = 0; h < 6; h++)
                s += wa[(((long)(b * 6 + h) * 256) + i0 + ii) * 256 + j0 + jj];
            a_s[ent] = s * inv6;
        }
        __syncthreads();
        #pragma unroll
        for (int jj = 0; jj < 32; jj += 4) {
            float xv0 = x_s[(jj + 0) * 128 + tid];
            float xv1 = x_s[(jj + 1) * 128 + tid];
            float xv2 = x_s[(jj + 2) * 128 + tid];
            float xv3 = x_s[(jj + 3) * 128 + tid];
            #pragma unroll
            for (int ii = 0; ii < 8; ii++) {
                float4 a4 = *(const float4*)&a_s[ii * 32 + jj];
                acc[ii] += a4.x * xv0 + a4.y * xv1 + a4.z * xv2 + a4.w * xv3;
            }
        }
        __syncthreads();
    }
    #pragma unroll
    for (int ii = 0; ii < 8; ii++)
        g_t[((long)b * 256 + i0 + ii) * 128 + tid] = acc[ii];
}

// ---------------------------------------------------------------------------
// Fused: gcn = relu(t @ W_w^T + W_b); out = gcn @ Wxx^T + Wxx_b;
//        n1 = gcn @ Wn1^T; n2 = gcn @ Wn2^T
// grid = 2048/8 = 256 blocks, 128 threads (thread = d), 8 rows per block
// ---------------------------------------------------------------------------
__global__ void __launch_bounds__(128) k_gcn_out(const float* __restrict__ Wb,
                                                 const float* __restrict__ Wx_w,
                                                 const float* __restrict__ Wxxb,
                                                 float* __restrict__ out) {
    __shared__ float t_s[8 * 128];
    __shared__ float g_s[8 * 128];
    __shared__ float wx_s[6 * 294];
    int r0  = blockIdx.x * 8;
    int tid = threadIdx.x;

    #pragma unroll
    for (int idx = tid; idx < 1024; idx += 128) t_s[idx] = g_t[r0 * 128 + idx];
    for (int idx = tid; idx < 1764; idx += 128) wx_s[idx] = Wx_w[idx];
    __syncthreads();

    // gcn
    float acc[8];
    #pragma unroll
    for (int ii = 0; ii < 8; ii++) acc[ii] = 0.0f;
    #pragma unroll 4
    for (int k = 0; k < 128; k += 4) {
        float wv0 = g_WwT[(k + 0) * 128 + tid];   // coalesced, L1-resident
        float wv1 = g_WwT[(k + 1) * 128 + tid];
        float wv2 = g_WwT[(k + 2) * 128 + tid];
        float wv3 = g_WwT[(k + 3) * 128 + tid];
        #pragma unroll
        for (int ii = 0; ii < 8; ii++) {
            float4 t4 = *(const float4*)&t_s[ii * 128 + k];   // broadcast LDS.128
            acc[ii] += t4.x * wv0 + t4.y * wv1 + t4.z * wv2 + t4.w * wv3;
        }
    }
    float bb = Wb[tid];
    #pragma unroll
    for (int ii = 0; ii < 8; ii++)
        g_s[ii * 128 + tid] = fmaxf(acc[ii] + bb, 0.0f);
    __syncthreads();

    // out
    float o[8];
    #pragma unroll
    for (int ii = 0; ii < 8; ii++) o[ii] = 0.0f;
    #pragma unroll 4
    for (int k = 0; k < 128; k += 4) {
        float wv0 = g_WxxT[(k + 0) * 128 + tid];
        float wv1 = g_WxxT[(k + 1) * 128 + tid];
        float wv2 = g_WxxT[(k + 2) * 128 + tid];
        float wv3 = g_WxxT[(k + 3) * 128 + tid];
        #pragma unroll
        for (int ii = 0; ii < 8; ii++) {
            float4 t4 = *(const float4*)&g_s[ii * 128 + k];
            o[ii] += t4.x * wv0 + t4.y * wv1 + t4.z * wv2 + t4.w * wv3;
        }
    }
    float ob = Wxxb[tid];
    #pragma unroll
    for (int ii = 0; ii < 8; ii++)
        out[(long)(r0 + ii) * 128 + tid] = o[ii] + ob;

    // n1/n2: 8 rows x 6 heads = 48 dot products of length 128
    if (tid < 48) {
        int ii = tid / 6, k = tid % 6;
        const float* g  = &g_s[ii * 128];
        const float* w1 = &wx_s[k * 294 + 6];          // Wn1 row k
        const float* w2 = &wx_s[k * 294 + 134];        // Wn2 row k
        float s1 = 0.0f, s2 = 0.0f;
        #pragma unroll 8
        for (int d = 0; d < 128; d++) { s1 += g[d] * w1[d]; s2 += g[d] * w2[d]; }
        g_n1[(long)(r0 + ii) * 8 + k] = s1;
        g_n2[(long)(r0 + ii) * 8 + k] = s2;
    }
}

// ---------------------------------------------------------------------------
// new_adj[b,k,i,j] = sum_h wa[b,h,i,j]*Wa[k,h] + n1[b,i,k] + n2[b,j,k]
//                  + sum_e e[b,i,j,e]*We[k,e] + Wx_b[k]
// grid = B*L = 2048 blocks (one per (b,i)), 256 threads (thread = j)
// ---------------------------------------------------------------------------
__global__ void __launch_bounds__(256) k_adj(const float* __restrict__ wa,
                                             const float* __restrict__ e,
                                             const float* __restrict__ Wx_w,
                                             const float* __restrict__ Wx_b,
                                             float* __restrict__ adj_out) {
    __shared__ float e_s[256 * 33];     // [j][ee], pad 33 -> conflict-free
    __shared__ float Wa_s[36];          // [k][h]
    __shared__ float We_s[192];         // [k][ee]
    __shared__ float n1b_s[12];         // n1[6] + bias[6]
    int b   = blockIdx.x >> 8;
    int i   = blockIdx.x & 255;
    int tid = threadIdx.x;

    // stage e[b,i,:, :] = 32KB contiguous, coalesced float4 copy
    const float4* e4 = (const float4*)(e + (((long)b * 256 + i) * 256) * 32);
    #pragma unroll
    for (int it = 0; it < 8; it++) {
        int    idx = tid + it * 256;
        float4 v   = e4[idx];
        int    j   = idx >> 3;
        int    e0  = (idx & 7) << 2;
        float* p   = &e_s[j * 33 + e0];
        p[0] = v.x; p[1] = v.y; p[2] = v.z; p[3] = v.w;
    }
    // wa values for this thread's j (coalesced per h), no cross-thread reuse
    float wv[6];
    #pragma unroll
    for (int h = 0; h < 6; h++)
        wv[h] = wa[(((long)(b * 6 + h) * 256) + i) * 256 + tid];
    // tiny constants
    if (tid < 36) Wa_s[tid] = Wx_w[(tid / 6) * 294 + tid % 6];
    if (tid >= 64 && tid < 256) {
        int t = tid - 64;
        We_s[t] = Wx_w[(t >> 5) * 294 + 262 + (t & 31)];
    }
    if (tid >= 40 && tid < 46) n1b_s[tid - 40]     = g_n1[((long)b * 256 + i) * 8 + (tid - 40)];
    if (tid >= 48 && tid < 54) n1b_s[6 + tid - 48] = Wx_b[tid - 48];
    // n2 for this thread's j
    const float4* n2p = (const float4*)&g_n2[((long)b * 256 + tid) * 8];
    float4 n2a = n2p[0], n2b = n2p[1];
    __syncthreads();

    float acc[6];
    acc[0] = n1b_s[0] + n1b_s[6]  + n2a.x;
    acc[1] = n1b_s[1] + n1b_s[7]  + n2a.y;
    acc[2] = n1b_s[2] + n1b_s[8]  + n2a.z;
    acc[3] = n1b_s[3] + n1b_s[9]  + n2a.w;
    acc[4] = n1b_s[4] + n1b_s[10] + n2b.x;
    acc[5] = n1b_s[5] + n1b_s[11] + n2b.y;

    #pragma unroll
    for (int h = 0; h < 6; h++) {
        float w = wv[h];
        #pragma unroll
        for (int k = 0; k < 6; k++) acc[k] += w * Wa_s[k * 6 + h];
    }
    const float* ep = &e_s[tid * 33];
    #pragma unroll
    for (int ee = 0; ee < 32; ee++) {
        float ev = ep[ee];
        #pragma unroll
        for (int k = 0; k < 6; k++) acc[k] += ev * We_s[k * 32 + ee];
    }

    long ob = ((long)(b * 6) * 65536) + (long)i * 256 + tid;
    #pragma unroll
    for (int k = 0; k < 6; k++)
        adj_out[ob + (long)k * 65536] = acc[k];   // coalesced per k
}

// ---------------------------------------------------------------------------
extern "C" void kernel_launch(void* const* d_in, const int* in_sizes, int n_in,
                              void* d_out, int out_size) {
    const float* x     = (const float*)d_in[0];
    const float* wa    = (const float*)d_in[1];
    const float* e     = (const float*)d_in[2];
    const float* W_w   = (const float*)d_in[3];
    const float* W_b   = (const float*)d_in[4];
    const float* Wx_w  = (const float*)d_in[5];
    const float* Wx_b  = (const float*)d_in[6];
    const float* Wxx_w = (const float*)d_in[7];
    const float* Wxx_b = (const float*)d_in[8];

    float* out     = (float*)d_out;            // (B,L,D) = 262144 floats
    float* adj_out = out + 8 * 256 * 128;      // (B,H,L,L) = 3145728 floats

    k_transpose<<<32, dim3(32, 8)>>>(W_w, Wxx_w);
    k_gcn_agg<<<256, 128>>>(x, wa);
    k_gcn_out<<<256, 128>>>(W_b, Wx_w, Wxx_b, out);
    k_adj<<<2048, 256>>>(wa, e, Wx_w, Wx_b, adj_out);
}

// round 2
// speedup vs baseline: 1.8996x; 1.8996x over previous
#include <cuda_runtime.h>

typedef unsigned long long u64;

// packed f32x2 helpers (sm_100+ PTX; doubles FFMA throughput)
__device__ __forceinline__ u64 pk2(float lo, float hi) {
    u64 r; asm("mov.b64 %0,{%1,%2};" : "=l"(r) : "f"(lo), "f"(hi)); return r;
}
__device__ __forceinline__ u64 fma2(u64 a, u64 b, u64 c) {
    u64 d; asm("fma.rn.f32x2 %0,%1,%2,%3;" : "=l"(d) : "l"(a), "l"(b), "l"(c)); return d;
}
__device__ __forceinline__ float sum2(u64 a) {
    float lo, hi; asm("mov.b64 {%0,%1},%2;" : "=f"(lo), "=f"(hi) : "l"(a)); return lo + hi;
}

// Scratch (allocation-free rule: __device__ globals)
__device__ float g_n1[2048 * 8];     // n1[row][k]
__device__ float g_n2T[6 * 2048];    // n2 transposed [k][row] -> coalesced reads in k_adj
__device__ float g_WwT[128 * 128];   // W_w transposed  [k][d]
__device__ float g_WxxT[128 * 128];  // Wxx_w transposed [k][d]

// ---------------------------------------------------------------------------
// Transpose W_w and Wxx_w (tiny)
// ---------------------------------------------------------------------------
__global__ void k_transpose(const float* __restrict__ Ww,
                            const float* __restrict__ Wxx) {
    __shared__ float tile[32][33];
    int m  = blockIdx.x >> 4;
    int t  = blockIdx.x & 15;
    int tr = (t >> 2) * 32, tc = (t & 3) * 32;
    const float* src = m ? Wxx : Ww;
    float*       dst = m ? g_WxxT : g_WwT;
    int tx = threadIdx.x, ty = threadIdx.y;
    #pragma unroll
    for (int r = ty; r < 32; r += 8)
        tile[r][tx] = src[(tr + r) * 128 + tc + tx];
    __syncthreads();
    #pragma unroll
    for (int r = ty; r < 32; r += 8)
        dst[(tc + r) * 128 + tr + tx] = tile[tx][r];
}

// ---------------------------------------------------------------------------
// Merged: t = mean_h(wa) @ x ; gcn = relu(t@W^T+b) ; out = gcn@Wxx^T+b ;
//         n1 = gcn@Wn1^T ; n2 = gcn@Wn2^T
// grid = B*(L/8) = 256 blocks, 256 threads (two 128-thread halves)
// ---------------------------------------------------------------------------
__global__ void __launch_bounds__(256) k_gcn(const float* __restrict__ x,
                                             const float* __restrict__ wa,
                                             const float* __restrict__ Wb,
                                             const float* __restrict__ Wx_w,
                                             const float* __restrict__ Wxxb,
                                             float* __restrict__ out) {
    __shared__ __align__(16) float x_s[2][32 * 128];
    __shared__ __align__(16) float a_s[2][8 * 32];
    __shared__ __align__(16) float tp_s[2][8 * 128];
    __shared__ __align__(16) float t_s[8 * 128];
    __shared__ __align__(16) float g_s[8 * 128];

    int b    = blockIdx.x >> 5;
    int i0   = (blockIdx.x & 31) << 3;
    int tid  = threadIdx.x;
    int lane = tid & 127;
    int half = tid >> 7;
    const float inv6 = 1.0f / 6.0f;

    // ---------- Phase A: aggregation, halves split the j-range ----------
    u64 acc2[8];
    #pragma unroll
    for (int ii = 0; ii < 8; ii++) acc2[ii] = 0ull;

    for (int jt = 0; jt < 4; jt++) {
        int j0 = half * 128 + jt * 32;
        const float4* xs = (const float4*)(x + ((long)b * 256 + j0) * 128);
        float4*       xd = (float4*)x_s[half];
        #pragma unroll
        for (int idx = lane; idx < 1024; idx += 128) xd[idx] = xs[idx];
        #pragma unroll
        for (int ent = lane; ent < 256; ent += 128) {
            int ii = ent >> 5, jj = ent & 31;
            float s = 0.0f;
            #pragma unroll
            for (int h = 0; h < 6; h++)
                s += wa[(((long)(b * 6 + h) * 256) + i0 + ii) * 256 + j0 + jj];
            a_s[half][ent] = s * inv6;
        }
        __syncthreads();
        const float* xh = x_s[half];
        const float* ah = a_s[half];
        #pragma unroll
        for (int jj = 0; jj < 32; jj += 2) {
            u64 xp = pk2(xh[jj * 128 + lane], xh[(jj + 1) * 128 + lane]);
            #pragma unroll
            for (int ii = 0; ii < 8; ii++) {
                u64 a2 = *(const u64*)&ah[ii * 32 + jj];
                acc2[ii] = fma2(a2, xp, acc2[ii]);
            }
        }
        __syncthreads();
    }
    #pragma unroll
    for (int ii = 0; ii < 8; ii++) tp_s[half][ii * 128 + lane] = sum2(acc2[ii]);
    __syncthreads();
    #pragma unroll
    for (int idx = tid; idx < 1024; idx += 256) t_s[idx] = tp_s[0][idx] + tp_s[1][idx];
    __syncthreads();

    // ---------- Phase B: gcn = relu(t @ W^T + b), halves split rows ----------
    u64 b2[4];
    #pragma unroll
    for (int r = 0; r < 4; r++) b2[r] = 0ull;
    #pragma unroll 8
    for (int k = 0; k < 128; k += 2) {
        u64 wp = pk2(g_WwT[k * 128 + lane], g_WwT[(k + 1) * 128 + lane]);
        #pragma unroll
        for (int r = 0; r < 4; r++) {
            u64 t2 = *(const u64*)&t_s[(half * 4 + r) * 128 + k];
            b2[r] = fma2(t2, wp, b2[r]);
        }
    }
    float bb = Wb[lane];
    #pragma unroll
    for (int r = 0; r < 4; r++)
        g_s[(half * 4 + r) * 128 + lane] = fmaxf(sum2(b2[r]) + bb, 0.0f);
    __syncthreads();

    // ---------- Phase C: out = gcn @ Wxx^T + b ----------
    u64 o2[4];
    #pragma unroll
    for (int r = 0; r < 4; r++) o2[r] = 0ull;
    #pragma unroll 8
    for (int k = 0; k < 128; k += 2) {
        u64 wp = pk2(g_WxxT[k * 128 + lane], g_WxxT[(k + 1) * 128 + lane]);
        #pragma unroll
        for (int r = 0; r < 4; r++) {
            u64 g2 = *(const u64*)&g_s[(half * 4 + r) * 128 + k];
            o2[r] = fma2(g2, wp, o2[r]);
        }
    }
    float ob = Wxxb[lane];
    int   r0 = blockIdx.x * 8;
    #pragma unroll
    for (int r = 0; r < 4; r++)
        out[(long)(r0 + half * 4 + r) * 128 + lane] = sum2(o2[r]) + ob;

    // ---------- Phase D: n1/n2 (48 dot products, weights L1-resident) ----------
    if (tid < 48) {
        int ii = tid / 6, k = tid % 6;
        const float* g  = &g_s[ii * 128];
        const float* w1 = Wx_w + k * 294 + 6;      // Wn1 row k
        const float* w2 = Wx_w + k * 294 + 134;    // Wn2 row k
        u64 s1 = 0ull, s2 = 0ull;
        #pragma unroll 8
        for (int d = 0; d < 128; d += 2) {
            u64 gp = *(const u64*)&g[d];
            s1 = fma2(gp, pk2(__ldg(&w1[d]), __ldg(&w1[d + 1])), s1);
            s2 = fma2(gp, pk2(__ldg(&w2[d]), __ldg(&w2[d + 1])), s2);
        }
        g_n1[(r0 + ii) * 8 + k]    = sum2(s1);
        g_n2T[k * 2048 + r0 + ii]  = sum2(s2);
    }
}

// ---------------------------------------------------------------------------
// new_adj[b,k,i,j] = sum_h wa[b,h,i,j]*Wa[k,h] + n1[b,i,k] + n2[b,j,k]
//                  + sum_e e[b,i,j,e]*We[k,e] + Wx_b[k]
// grid = B*L = 2048 blocks (one per (b,i)), 256 threads (thread = j)
// ---------------------------------------------------------------------------
__global__ void __launch_bounds__(256) k_adj(const float* __restrict__ wa,
                                             const float* __restrict__ e,
                                             const float* __restrict__ Wx_w,
                                             const float* __restrict__ Wx_b,
                                             float* __restrict__ adj_out) {
    __shared__ __align__(16) float e_s[256 * 36];  // [j][ee] pad 36: .128 both sides, conflict-free
    __shared__ __align__(16) float Wa_s[40];       // [k*6+h]
    __shared__ __align__(16) float We_s[200];      // [k*32+ee]
    __shared__ __align__(16) float n1b_s[16];      // n1 @0..5, bias @8..13
    int b   = blockIdx.x >> 8;
    int i   = blockIdx.x & 255;
    int tid = threadIdx.x;

    // stage e[b,i,:,:] (32KB contiguous) — coalesced float4 in, .128 out
    const float4* e4 = (const float4*)(e + (((long)b * 256 + i) * 256) * 32);
    #pragma unroll
    for (int it = 0; it < 8; it++) {
        int    idx = tid + it * 256;
        float4 v   = e4[idx];
        int    j   = idx >> 3;
        int    c   = idx & 7;
        *(float4*)&e_s[j * 36 + c * 4] = v;
    }
    float wv[6];
    #pragma unroll
    for (int h = 0; h < 6; h++)
        wv[h] = wa[(((long)(b * 6 + h) * 256) + i) * 256 + tid];
    if (tid < 36) Wa_s[tid] = Wx_w[(tid / 6) * 294 + tid % 6];
    if (tid >= 64 && tid < 256) {
        int t = tid - 64;
        We_s[t] = Wx_w[(t >> 5) * 294 + 262 + (t & 31)];
    }
    if (tid >= 40 && tid < 46) n1b_s[tid - 40]     = g_n1[((long)b * 256 + i) * 8 + (tid - 40)];
    if (tid >= 48 && tid < 54) n1b_s[8 + tid - 48] = Wx_b[tid - 48];
    // n2 transposed: 6 coalesced loads
    float n2v[6];
    #pragma unroll
    for (int k = 0; k < 6; k++) n2v[k] = g_n2T[k * 2048 + b * 256 + tid];
    __syncthreads();

    u64 acc2[6];
    #pragma unroll
    for (int k = 0; k < 6; k++) acc2[k] = 0ull;

    // adj term: 3 packed h-pairs x 6 k
    u64 wp0 = pk2(wv[0], wv[1]), wp1 = pk2(wv[2], wv[3]), wp2 = pk2(wv[4], wv[5]);
    #pragma unroll
    for (int k = 0; k < 6; k++) {
        acc2[k] = fma2(*(const u64*)&Wa_s[k * 6 + 0], wp0, acc2[k]);
        acc2[k] = fma2(*(const u64*)&Wa_s[k * 6 + 2], wp1, acc2[k]);
        acc2[k] = fma2(*(const u64*)&Wa_s[k * 6 + 4], wp2, acc2[k]);
    }

    // e term: 8 x LDS.128 (conflict-free), 16 packed ee-pairs x 6 k
    const float4* ep = (const float4*)&e_s[tid * 36];
    #pragma unroll
    for (int q = 0; q < 8; q++) {
        float4 v = ep[q];
        u64 ev0 = pk2(v.x, v.y);
        u64 ev1 = pk2(v.z, v.w);
        #pragma unroll
        for (int k = 0; k < 6; k++) {
            acc2[k] = fma2(ev0, *(const u64*)&We_s[k * 32 + q * 4 + 0], acc2[k]);
            acc2[k] = fma2(ev1, *(const u64*)&We_s[k * 32 + q * 4 + 2], acc2[k]);
        }
    }

    long ob = ((long)(b * 6) * 65536) + (long)i * 256 + tid;
    #pragma unroll
    for (int k = 0; k < 6; k++)
        adj_out[ob + (long)k * 65536] = sum2(acc2[k]) + n1b_s[k] + n1b_s[8 + k] + n2v[k];
}

// ---------------------------------------------------------------------------
extern "C" void kernel_launch(void* const* d_in, const int* in_sizes, int n_in,
                              void* d_out, int out_size) {
    const float* x     = (const float*)d_in[0];
    const float* wa    = (const float*)d_in[1];
    const float* e     = (const float*)d_in[2];
    const float* W_w   = (const float*)d_in[3];
    const float* W_b   = (const float*)d_in[4];
    const float* Wx_w  = (const float*)d_in[5];
    const float* Wx_b  = (const float*)d_in[6];
    const float* Wxx_w = (const float*)d_in[7];
    const float* Wxx_b = (const float*)d_in[8];

    float* out     = (float*)d_out;            // (B,L,D) = 262144 floats
    float* adj_out = out + 8 * 256 * 128;      // (B,H,L,L) = 3145728 floats

    k_transpose<<<32, dim3(32, 8)>>>(W_w, Wxx_w);
    k_gcn<<<256, 256>>>(x, wa, W_b, Wx_w, Wxx_b, out);
    k_adj<<<2048, 256>>>(wa, e, Wx_w, Wx_b, adj_out);
}